// round 16
// baseline (speedup 1.0000x reference)
#include <cuda_runtime.h>
#include <cuda_fp16.h>
#include <cstdint>

// B=4, S=4096, H=4096, D=1024
#define BATCH 4
#define SEQ   4096
#define HID   4096
#define DHEAD 1024

// Scratch (device globals: allocation-free per harness rules)
__device__ __align__(16) __half g_xh    [ (size_t)BATCH * SEQ * HID   ]; // 134 MB fp16 x
__device__ __align__(16) __half g_wqkvT [ (size_t)3 * DHEAD * HID     ]; //  25 MB Wqkv^T fp16
__device__ __align__(16) __half g_woT   [ (size_t)HID * DHEAD         ]; //   8 MB Wo^T fp16
__device__ __align__(16) __half g_qkvh  [ (size_t)BATCH * SEQ * 3 * DHEAD ]; // 100 MB (q,k used)
__device__ __align__(16) __half g_vth   [ (size_t)BATCH * DHEAD * SEQ ]; //  33 MB V^T fp16
__device__ float                g_attn  [ (size_t)BATCH * SEQ * SEQ   ]; // 268 MB fp32 scores
__device__ __align__(16) __half g_attnh [ (size_t)BATCH * SEQ * SEQ   ]; // 134 MB fp16 P
__device__ __align__(16) __half g_aouth [ (size_t)BATCH * SEQ * DHEAD ]; //  33 MB fp16 attn-out

#define BM 128
#define BN 128
#define BK 64
#define NSTAGE 3
#define STAGE_BYTES 32768      // A 16KB + B 16KB (half, 128 rows x 128B)

__device__ __forceinline__ uint32_t h2_bits(__half2 h) {
    return *reinterpret_cast<uint32_t*>(&h);
}

__device__ __forceinline__ void cp_async16_s(uint32_t s, const void* g) {
    asm volatile("cp.async.cg.shared.global [%0], [%1], 16;" :: "r"(s), "l"(g));
}
__device__ __forceinline__ void cp_commit() { asm volatile("cp.async.commit_group;"); }

__device__ __forceinline__ void ldsm4(uint32_t& r0, uint32_t& r1, uint32_t& r2,
                                      uint32_t& r3, uint32_t a) {
    asm volatile("ldmatrix.sync.aligned.m8n8.x4.shared.b16 {%0,%1,%2,%3}, [%4];"
                 : "=r"(r0), "=r"(r1), "=r"(r2), "=r"(r3) : "r"(a));
}

__device__ __forceinline__ void mma_f16(float* c, const uint32_t* a, const uint32_t* b) {
    asm volatile(
        "mma.sync.aligned.m16n8k16.row.col.f32.f16.f16.f32 "
        "{%0,%1,%2,%3}, {%4,%5,%6,%7}, {%8,%9}, {%0,%1,%2,%3};"
        : "+f"(c[0]), "+f"(c[1]), "+f"(c[2]), "+f"(c[3])
        : "r"(a[0]), "r"(a[1]), "r"(a[2]), "r"(a[3]), "r"(b[0]), "r"(b[1]));
}

// NT fp16 GEMM: C[M,N] = alpha * A(K-major) . B^T (B stored [N,K] K-major) (+bias)
// CTA 128x128, 256 threads / 8 warps (warp tile 64x32), BK=64, 3-stage cp.async,
// SW128 swizzle + ldmatrix. One barrier per mainloop iter.
// MODE 0: fp32 C32.  MODE 1: fp16 C16.  MODE 2: qkv split (n<2048 -> C16;
//   v-region CTAs transpose through SMEM and write V^T with coalesced 16B stores).
template <int MODE>
__global__ __launch_bounds__(256, 2) void hgemm(
    const __half* __restrict__ A, int lda, long long sA,
    const __half* __restrict__ B, int ldb, long long sB,
    const float* __restrict__ bias,
    float* __restrict__ C32, __half* __restrict__ C16, __half* __restrict__ VT,
    int ldc, long long sC, int K, float alpha)
{
    extern __shared__ char dsm[];
    const uint32_t smBase = (uint32_t)__cvta_generic_to_shared(dsm);

    const int tid = threadIdx.x;
    const int bx = blockIdx.x, by = blockIdx.y, bz = blockIdx.z;

    const __half* Ag = A + (long long)bz * sA + (size_t)by * BM * lda;
    const __half* Bg = B + (long long)bz * sB + (size_t)bx * BN * ldb;

    // Loader: per stage, A and B each 1024 16B-chunks; 4 per thread per array
    auto load_stage = [&](int st, int k0) {
        const uint32_t sa = smBase + st * STAGE_BYTES;
        const uint32_t sb = sa + 16384;
        #pragma unroll
        for (int i = 0; i < 4; i++) {
            const int ch = tid + i * 256;
            const int r = ch >> 3, c = ch & 7;
            cp_async16_s(sa + (uint32_t)(r * 128 + ((c ^ (r & 7)) << 4)),
                         Ag + (size_t)r * lda + k0 + c * 8);
        }
        #pragma unroll
        for (int i = 0; i < 4; i++) {
            const int ch = tid + i * 256;
            const int r = ch >> 3, c = ch & 7;
            cp_async16_s(sb + (uint32_t)(r * 128 + ((c ^ (r & 7)) << 4)),
                         Bg + (size_t)r * ldb + k0 + c * 8);
        }
        cp_commit();
    };

    // 8 warps as 2(M) x 4(N); warp tile 64x32
    const int lane = tid & 31;
    const int wid  = tid >> 5;
    const int m0 = (wid & 1) * 64;
    const int n0 = (wid >> 1) * 32;
    const int g  = lane >> 2;
    const int tg = lane & 3;
    const int sub = lane & 7;

    float acc[4][4][4];
    #pragma unroll
    for (int mt = 0; mt < 4; mt++)
        #pragma unroll
        for (int nt = 0; nt < 4; nt++)
            #pragma unroll
            for (int i = 0; i < 4; i++) acc[mt][nt][i] = 0.f;

    const int nIter = K / BK;
    load_stage(0, 0);
    load_stage(1, BK);

    for (int it = 0; it < nIter; ++it) {
        if (it + 1 < nIter) asm volatile("cp.async.wait_group 1;");
        else                asm volatile("cp.async.wait_group 0;");
        __syncthreads();   // single barrier: orders stage-(it) RAW and stage-(it+2) WAR
        if (it + 2 < nIter) load_stage((it + 2) % NSTAGE, (it + 2) * BK);

        const uint32_t sa = smBase + (it % NSTAGE) * STAGE_BYTES;
        const uint32_t sb = sa + 16384;

        #pragma unroll
        for (int ks4 = 0; ks4 < 4; ks4++) {          // k16 slice = ks4*16
            uint32_t af[4][4];
            #pragma unroll
            for (int mt = 0; mt < 4; mt++) {
                const int row = m0 + mt * 16 + ((lane >> 3) & 1) * 8 + sub;
                const int chunk = 2 * ks4 + (lane >> 4);
                ldsm4(af[mt][0], af[mt][1], af[mt][2], af[mt][3],
                      sa + (uint32_t)(row * 128 + ((chunk ^ (row & 7)) << 4)));
            }
            uint32_t bf[4][2];
            #pragma unroll
            for (int p = 0; p < 2; p++) {
                const int row = n0 + p * 16 + (lane >> 4) * 8 + sub;
                const int chunk = 2 * ks4 + ((lane >> 3) & 1);
                ldsm4(bf[2 * p][0], bf[2 * p][1], bf[2 * p + 1][0], bf[2 * p + 1][1],
                      sb + (uint32_t)(row * 128 + ((chunk ^ (row & 7)) << 4)));
            }
            #pragma unroll
            for (int mt = 0; mt < 4; mt++)
                #pragma unroll
                for (int nt = 0; nt < 4; nt++)
                    mma_f16(acc[mt][nt], af[mt], bf[nt]);
        }
    }

    // ---------------- Epilogue ----------------
    const bool is_v = (MODE == 2) && (bx >= 16);     // v region: n >= 2048 (16*128)

    if (is_v) {
        // Transpose through SMEM (pipeline buffers are dead), then coalesced V^T.
        __syncthreads();   // all warps done reading stage SMEM (CTA-uniform branch)
        __half* tile = reinterpret_cast<__half*>(dsm);   // [n_local][m_local], stride 136
        #pragma unroll
        for (int mt = 0; mt < 4; mt++) {
            #pragma unroll
            for (int nt = 0; nt < 4; nt++) {
                const int r = m0 + mt * 16 + g;
                const int c = n0 + nt * 8 + 2 * tg;
                const int nglob = bx * BN + c;
                const float b0 = bias[nglob], b1 = bias[nglob + 1];
                tile[(c)     * 136 + r]     = __float2half_rn(acc[mt][nt][0] * alpha + b0);
                tile[(c + 1) * 136 + r]     = __float2half_rn(acc[mt][nt][1] * alpha + b1);
                tile[(c)     * 136 + r + 8] = __float2half_rn(acc[mt][nt][2] * alpha + b0);
                tile[(c + 1) * 136 + r + 8] = __float2half_rn(acc[mt][nt][3] * alpha + b1);
            }
        }
        __syncthreads();
        const int bidx = (by * BM) >> 12;          // batch of this row block
        const int s0   = (by * BM) & 4095;         // seq offset
        const int d0   = bx * BN - 2048;           // head-dim offset
        #pragma unroll
        for (int i = 0; i < 8; i++) {
            const int u = tid + i * 256;           // 0..2047 uint4 chunks
            const int row = u >> 4;                // n_local 0..127
            const int c16 = (u & 15) * 8;          // half offset in row
            *reinterpret_cast<uint4*>(
                VT + ((size_t)(bidx * DHEAD + d0 + row)) * SEQ + s0 + c16) =
                *reinterpret_cast<const uint4*>(tile + row * 136 + c16);
        }
        return;
    }

    #pragma unroll
    for (int mt = 0; mt < 4; mt++) {
        #pragma unroll
        for (int nt = 0; nt < 4; nt++) {
            const int r = m0 + mt * 16 + g;
            const int c = n0 + nt * 8 + 2 * tg;
            const int nglob = bx * BN + c;
            float b0 = 0.f, b1 = 0.f;
            if (bias) { b0 = bias[nglob]; b1 = bias[nglob + 1]; }
            const float v00 = acc[mt][nt][0] * alpha + b0;
            const float v01 = acc[mt][nt][1] * alpha + b1;
            const float v10 = acc[mt][nt][2] * alpha + b0;
            const float v11 = acc[mt][nt][3] * alpha + b1;
            const int m_lo = by * BM + r, m_hi = m_lo + 8;
            if (MODE == 0) {
                float* Cg = C32 + (long long)bz * sC;
                *reinterpret_cast<float2*>(&Cg[(size_t)m_lo * ldc + nglob]) =
                    make_float2(v00, v01);
                *reinterpret_cast<float2*>(&Cg[(size_t)m_hi * ldc + nglob]) =
                    make_float2(v10, v11);
            } else {
                __half* Cg = C16 + (long long)bz * sC;
                *reinterpret_cast<__half2*>(&Cg[(size_t)m_lo * ldc + nglob]) =
                    __floats2half2_rn(v00, v01);
                *reinterpret_cast<__half2*>(&Cg[(size_t)m_hi * ldc + nglob]) =
                    __floats2half2_rn(v10, v11);
            }
        }
    }
}

// fp32 -> fp16 elementwise (float4 -> 2x half2), grid-stride
__global__ __launch_bounds__(256) void f2h_kernel(
    const float4* __restrict__ in, uint2* __restrict__ out, size_t n4)
{
    for (size_t i = (size_t)blockIdx.x * blockDim.x + threadIdx.x; i < n4;
         i += (size_t)gridDim.x * blockDim.x) {
        float4 v = in[i];
        uint2 o;
        o.x = h2_bits(__floats2half2_rn(v.x, v.y));
        o.y = h2_bits(__floats2half2_rn(v.z, v.w));
        out[i] = o;
    }
}

// out_h[c][r] = half(in[r][c]); R, C multiples of 32
__global__ __launch_bounds__(256) void transpose_f2h(
    const float* __restrict__ in, __half* __restrict__ out, int R, int C)
{
    __shared__ float t[32][33];
    const int c = blockIdx.x * 32 + threadIdx.x;
    const int r0 = blockIdx.y * 32;
    for (int i = threadIdx.y; i < 32; i += 8)
        t[i][threadIdx.x] = in[(size_t)(r0 + i) * C + c];
    __syncthreads();
    const int rr = r0 + threadIdx.x;
    const int cc = blockIdx.x * 32;
    for (int i = threadIdx.y; i < 32; i += 8)
        out[(size_t)(cc + i) * R + rr] = __float2half_rn(t[threadIdx.x][i]);
}

// Row softmax over 4096 cols: read fp32 scores, write fp16 P. One block per row.
__global__ __launch_bounds__(256) void softmax_h(
    const float* __restrict__ P, __half* __restrict__ Ph)
{
    const size_t row = blockIdx.x;
    const float2* p2 = reinterpret_cast<const float2*>(P + row * (size_t)SEQ);
    __half2* o2 = reinterpret_cast<__half2*>(Ph + row * (size_t)SEQ);
    const int tid = threadIdx.x;

    float2 v[8];
    float mx = -1e30f;
    #pragma unroll
    for (int i = 0; i < 8; i++) {
        v[i] = p2[i * 256 + tid];
        mx = fmaxf(mx, fmaxf(v[i].x, v[i].y));
    }

    __shared__ float red[8];
    #pragma unroll
    for (int off = 16; off; off >>= 1)
        mx = fmaxf(mx, __shfl_xor_sync(0xFFFFFFFFu, mx, off));
    if ((tid & 31) == 0) red[tid >> 5] = mx;
    __syncthreads();
    mx = red[0];
    #pragma unroll
    for (int w = 1; w < 8; w++) mx = fmaxf(mx, red[w]);

    float sum = 0.f;
    #pragma unroll
    for (int i = 0; i < 8; i++) {
        v[i].x = __expf(v[i].x - mx);
        v[i].y = __expf(v[i].y - mx);
        sum += v[i].x + v[i].y;
    }
    __syncthreads();
    #pragma unroll
    for (int off = 16; off; off >>= 1)
        sum += __shfl_xor_sync(0xFFFFFFFFu, sum, off);
    if ((tid & 31) == 0) red[tid >> 5] = sum;
    __syncthreads();
    sum = 0.f;
    #pragma unroll
    for (int w = 0; w < 8; w++) sum += red[w];

    const float inv = 1.f / sum;
    #pragma unroll
    for (int i = 0; i < 8; i++)
        o2[i * 256 + tid] = __floats2half2_rn(v[i].x * inv, v[i].y * inv);
}

extern "C" void kernel_launch(void* const* d_in, const int* in_sizes, int n_in,
                              void* d_out, int out_size)
{
    const float* x    = (const float*)d_in[0];
    const float* Wqkv = (const float*)d_in[1];
    const float* bqkv = (const float*)d_in[2];
    const float* Wo   = (const float*)d_in[3];
    const float* bo   = (const float*)d_in[4];
    float* out = (float*)d_out;

    __half *xh, *wqkvT, *woT, *qkvh, *vth, *attnh, *aouth;
    float *attn;
    cudaGetSymbolAddress((void**)&xh,    g_xh);
    cudaGetSymbolAddress((void**)&wqkvT, g_wqkvT);
    cudaGetSymbolAddress((void**)&woT,   g_woT);
    cudaGetSymbolAddress((void**)&qkvh,  g_qkvh);
    cudaGetSymbolAddress((void**)&vth,   g_vth);
    cudaGetSymbolAddress((void**)&attn,  g_attn);
    cudaGetSymbolAddress((void**)&attnh, g_attnh);
    cudaGetSymbolAddress((void**)&aouth, g_aouth);

    const int SMEM_DYN = NSTAGE * STAGE_BYTES;   // 98304 B
    cudaFuncSetAttribute(hgemm<0>, cudaFuncAttributeMaxDynamicSharedMemorySize, SMEM_DYN);
    cudaFuncSetAttribute(hgemm<1>, cudaFuncAttributeMaxDynamicSharedMemorySize, SMEM_DYN);
    cudaFuncSetAttribute(hgemm<2>, cudaFuncAttributeMaxDynamicSharedMemorySize, SMEM_DYN);

    const int BS = BATCH * SEQ;                      // 16384
    const long long sQKV = (long long)SEQ * 3 * DHEAD;
    const long long sATT = (long long)SEQ * SEQ;
    const long long sVT  = (long long)DHEAD * SEQ;
    const long long sOUT = (long long)SEQ * DHEAD;
    const float scale = 0.03125f;                    // 1/sqrt(1024)
    dim3 blk(256);

    // 0. fp16 conversions: x (elementwise), Wqkv^T and Wo^T (transpose)
    f2h_kernel<<<2048, 256>>>((const float4*)x, (uint2*)xh,
                              (size_t)BS * HID / 4);
    transpose_f2h<<<dim3(3 * DHEAD / 32, HID / 32), dim3(32, 8)>>>(Wqkv, wqkvT, HID, 3 * DHEAD);
    transpose_f2h<<<dim3(HID / 32, DHEAD / 32), dim3(32, 8)>>>(Wo, woT, DHEAD, HID);

    // 1. qkv = x @ Wqkv + bqkv  [16384 x 3072, K=4096]; q,k -> qkvh, v -> vth^T
    hgemm<2><<<dim3(3 * DHEAD / BN, BS / BM, 1), blk, SMEM_DYN>>>(
        xh, HID, 0, wqkvT, HID, 0, bqkv,
        nullptr, qkvh, vth, 3 * DHEAD, 0, HID, 1.f);

    // 2. scores = scale * Q @ K^T  (batched, K=1024) -> fp32 attn
    hgemm<0><<<dim3(SEQ / BN, SEQ / BM, BATCH), blk, SMEM_DYN>>>(
        qkvh, 3 * DHEAD, sQKV, qkvh + DHEAD, 3 * DHEAD, sQKV, nullptr,
        attn, nullptr, nullptr, SEQ, sATT, DHEAD, scale);

    // 3. softmax rows -> fp16 P
    softmax_h<<<BS, 256>>>(attn, attnh);

    // 4. out = P @ V  (batched, K=4096; B = V^T [1024][4096]) -> fp16 aout
    hgemm<1><<<dim3(DHEAD / BN, SEQ / BM, BATCH), blk, SMEM_DYN>>>(
        attnh, SEQ, sATT, vth, SEQ, sVT, nullptr,
        nullptr, aouth, nullptr, DHEAD, sOUT, SEQ, 1.f);

    // 5. y = out @ Wo + bo  [16384 x 4096, K=1024] -> fp32
    hgemm<0><<<dim3(HID / BN, BS / BM, 1), blk, SMEM_DYN>>>(
        aouth, DHEAD, 0, woT, DHEAD, 0, bo,
        out, nullptr, nullptr, HID, 0, DHEAD, 1.f);
}

// round 17
// speedup vs baseline: 1.0024x; 1.0024x over previous
#include <cuda_runtime.h>
#include <cuda_fp16.h>
#include <cstdint>

// B=4, S=4096, H=4096, D=1024
#define BATCH 4
#define SEQ   4096
#define HID   4096
#define DHEAD 1024

// Scratch (device globals: allocation-free per harness rules)
__device__ __align__(16) __half g_xh    [ (size_t)BATCH * SEQ * HID   ]; // 134 MB fp16 x
__device__ __align__(16) __half g_wqkvT [ (size_t)3 * DHEAD * HID     ]; //  25 MB Wqkv^T fp16
__device__ __align__(16) __half g_woT   [ (size_t)HID * DHEAD         ]; //   8 MB Wo^T fp16
__device__ __align__(16) __half g_qkvh  [ (size_t)BATCH * SEQ * 3 * DHEAD ]; // 100 MB (q,k used)
__device__ __align__(16) __half g_vth   [ (size_t)BATCH * DHEAD * SEQ ]; //  33 MB V^T fp16
__device__ float                g_attn  [ (size_t)BATCH * SEQ * SEQ   ]; // 268 MB fp32 scores
__device__ __align__(16) __half g_attnh [ (size_t)BATCH * SEQ * SEQ   ]; // 134 MB fp16 P
__device__ __align__(16) __half g_aouth [ (size_t)BATCH * SEQ * DHEAD ]; //  33 MB fp16 attn-out

#define BM 128
#define BN 128
#define BK 64
#define NSTAGE 3
#define STAGE_BYTES 32768      // A 16KB + B 16KB (half, 128 rows x 128B)

__device__ __forceinline__ uint32_t h2_bits(__half2 h) {
    return *reinterpret_cast<uint32_t*>(&h);
}

__device__ __forceinline__ void cp_async16_s(uint32_t s, const void* g) {
    asm volatile("cp.async.cg.shared.global [%0], [%1], 16;" :: "r"(s), "l"(g));
}
__device__ __forceinline__ void cp_commit() { asm volatile("cp.async.commit_group;"); }

__device__ __forceinline__ void ldsm4(uint32_t& r0, uint32_t& r1, uint32_t& r2,
                                      uint32_t& r3, uint32_t a) {
    asm volatile("ldmatrix.sync.aligned.m8n8.x4.shared.b16 {%0,%1,%2,%3}, [%4];"
                 : "=r"(r0), "=r"(r1), "=r"(r2), "=r"(r3) : "r"(a));
}

__device__ __forceinline__ void mma_f16(float* c, const uint32_t* a, const uint32_t* b) {
    asm volatile(
        "mma.sync.aligned.m16n8k16.row.col.f32.f16.f16.f32 "
        "{%0,%1,%2,%3}, {%4,%5,%6,%7}, {%8,%9}, {%0,%1,%2,%3};"
        : "+f"(c[0]), "+f"(c[1]), "+f"(c[2]), "+f"(c[3])
        : "r"(a[0]), "r"(a[1]), "r"(a[2]), "r"(a[3]), "r"(b[0]), "r"(b[1]));
}

// NT fp16 GEMM: C[M,N] = alpha * A(K-major) . B^T (B stored [N,K] K-major) (+bias)
// CTA 128x128, 256 threads / 8 warps (warp tile 64x32), BK=64, 3-stage cp.async,
// SW128 swizzle + ldmatrix, warp-staggered k16 phases (de-convoys LDSM bursts).
// MODE 0: fp32 C32.  MODE 1: fp16 C16.  MODE 2: qkv split (n<2048 -> C16; v -> VT^T).
template <int MODE>
__global__ __launch_bounds__(256, 2) void hgemm(
    const __half* __restrict__ A, int lda, long long sA,
    const __half* __restrict__ B, int ldb, long long sB,
    const float* __restrict__ bias,
    float* __restrict__ C32, __half* __restrict__ C16, __half* __restrict__ VT,
    int ldc, long long sC, int K, float alpha)
{
    extern __shared__ char dsm[];
    const uint32_t smBase = (uint32_t)__cvta_generic_to_shared(dsm);

    const int tid = threadIdx.x;
    const int bx = blockIdx.x, by = blockIdx.y, bz = blockIdx.z;

    const __half* Ag = A + (long long)bz * sA + (size_t)by * BM * lda;
    const __half* Bg = B + (long long)bz * sB + (size_t)bx * BN * ldb;

    // Loader: per stage, A and B each 1024 16B-chunks; 4 per thread per array
    auto load_stage = [&](int st, int k0) {
        const uint32_t sa = smBase + st * STAGE_BYTES;
        const uint32_t sb = sa + 16384;
        #pragma unroll
        for (int i = 0; i < 4; i++) {
            const int ch = tid + i * 256;
            const int r = ch >> 3, c = ch & 7;
            cp_async16_s(sa + (uint32_t)(r * 128 + ((c ^ (r & 7)) << 4)),
                         Ag + (size_t)r * lda + k0 + c * 8);
        }
        #pragma unroll
        for (int i = 0; i < 4; i++) {
            const int ch = tid + i * 256;
            const int r = ch >> 3, c = ch & 7;
            cp_async16_s(sb + (uint32_t)(r * 128 + ((c ^ (r & 7)) << 4)),
                         Bg + (size_t)r * ldb + k0 + c * 8);
        }
        cp_commit();
    };

    // 8 warps as 2(M) x 4(N); warp tile 64x32
    const int lane = tid & 31;
    const int wid  = tid >> 5;
    const int m0 = (wid & 1) * 64;
    const int n0 = (wid >> 1) * 32;
    const int g  = lane >> 2;
    const int tg = lane & 3;
    const int sub = lane & 7;
    const int koff = (wid >> 2) * 2;   // stagger: warps 0-3 start k16-slice 0, warps 4-7 slice 2

    float acc[4][4][4];
    #pragma unroll
    for (int mt = 0; mt < 4; mt++)
        #pragma unroll
        for (int nt = 0; nt < 4; nt++)
            #pragma unroll
            for (int i = 0; i < 4; i++) acc[mt][nt][i] = 0.f;

    const int nIter = K / BK;
    load_stage(0, 0);
    load_stage(1, BK);

    for (int it = 0; it < nIter; ++it) {
        if (it + 1 < nIter) asm volatile("cp.async.wait_group 1;");
        else                asm volatile("cp.async.wait_group 0;");
        __syncthreads();   // single barrier: orders stage-(it) RAW and stage-(it+2) WAR
        if (it + 2 < nIter) load_stage((it + 2) % NSTAGE, (it + 2) * BK);

        const uint32_t sa = smBase + (it % NSTAGE) * STAGE_BYTES;
        const uint32_t sb = sa + 16384;

        #pragma unroll
        for (int s = 0; s < 4; s++) {                // k16 slice, staggered per warp half
            const int ks4 = (s + koff) & 3;
            uint32_t af[4][4];
            #pragma unroll
            for (int mt = 0; mt < 4; mt++) {
                const int row = m0 + mt * 16 + ((lane >> 3) & 1) * 8 + sub;
                const int chunk = 2 * ks4 + (lane >> 4);
                ldsm4(af[mt][0], af[mt][1], af[mt][2], af[mt][3],
                      sa + (uint32_t)(row * 128 + ((chunk ^ (row & 7)) << 4)));
            }
            uint32_t bf[4][2];
            #pragma unroll
            for (int p = 0; p < 2; p++) {
                const int row = n0 + p * 16 + (lane >> 4) * 8 + sub;
                const int chunk = 2 * ks4 + ((lane >> 3) & 1);
                ldsm4(bf[2 * p][0], bf[2 * p][1], bf[2 * p + 1][0], bf[2 * p + 1][1],
                      sb + (uint32_t)(row * 128 + ((chunk ^ (row & 7)) << 4)));
            }
            #pragma unroll
            for (int mt = 0; mt < 4; mt++)
                #pragma unroll
                for (int nt = 0; nt < 4; nt++)
                    mma_f16(acc[mt][nt], af[mt], bf[nt]);
        }
    }

    // Epilogue (R14 direct-store version; SMEM-transpose variant measured slower)
    const bool is_v = (MODE == 2) && (bx >= 16);     // v region: n >= 2048 (16*128)
    #pragma unroll
    for (int mt = 0; mt < 4; mt++) {
        #pragma unroll
        for (int nt = 0; nt < 4; nt++) {
            const int r = m0 + mt * 16 + g;
            const int c = n0 + nt * 8 + 2 * tg;
            const int nglob = bx * BN + c;
            float b0 = 0.f, b1 = 0.f;
            if (bias) { b0 = bias[nglob]; b1 = bias[nglob + 1]; }
            const float v00 = acc[mt][nt][0] * alpha + b0;
            const float v01 = acc[mt][nt][1] * alpha + b1;
            const float v10 = acc[mt][nt][2] * alpha + b0;
            const float v11 = acc[mt][nt][3] * alpha + b1;
            const int m_lo = by * BM + r, m_hi = m_lo + 8;
            if (MODE == 0) {
                float* Cg = C32 + (long long)bz * sC;
                *reinterpret_cast<float2*>(&Cg[(size_t)m_lo * ldc + nglob]) =
                    make_float2(v00, v01);
                *reinterpret_cast<float2*>(&Cg[(size_t)m_hi * ldc + nglob]) =
                    make_float2(v10, v11);
            } else if (MODE == 1 || !is_v) {
                __half* Cg = C16 + (long long)bz * sC;
                *reinterpret_cast<__half2*>(&Cg[(size_t)m_lo * ldc + nglob]) =
                    __floats2half2_rn(v00, v01);
                *reinterpret_cast<__half2*>(&Cg[(size_t)m_hi * ldc + nglob]) =
                    __floats2half2_rn(v10, v11);
            } else {
                // V region: write V^T [b][d][s]
                const int d = nglob - 2048;
                const int b_lo = m_lo >> 12, s_lo = m_lo & 4095;
                const int b_hi = m_hi >> 12, s_hi = m_hi & 4095;
                VT[((size_t)b_lo * DHEAD + d)     * SEQ + s_lo] = __float2half_rn(v00);
                VT[((size_t)b_lo * DHEAD + d + 1) * SEQ + s_lo] = __float2half_rn(v01);
                VT[((size_t)b_hi * DHEAD + d)     * SEQ + s_hi] = __float2half_rn(v10);
                VT[((size_t)b_hi * DHEAD + d + 1) * SEQ + s_hi] = __float2half_rn(v11);
            }
        }
    }
}

// fp32 -> fp16 elementwise (float4 -> 2x half2), grid-stride
__global__ __launch_bounds__(256) void f2h_kernel(
    const float4* __restrict__ in, uint2* __restrict__ out, size_t n4)
{
    for (size_t i = (size_t)blockIdx.x * blockDim.x + threadIdx.x; i < n4;
         i += (size_t)gridDim.x * blockDim.x) {
        float4 v = in[i];
        uint2 o;
        o.x = h2_bits(__floats2half2_rn(v.x, v.y));
        o.y = h2_bits(__floats2half2_rn(v.z, v.w));
        out[i] = o;
    }
}

// out_h[c][r] = half(in[r][c]); R, C multiples of 32
__global__ __launch_bounds__(256) void transpose_f2h(
    const float* __restrict__ in, __half* __restrict__ out, int R, int C)
{
    __shared__ float t[32][33];
    const int c = blockIdx.x * 32 + threadIdx.x;
    const int r0 = blockIdx.y * 32;
    for (int i = threadIdx.y; i < 32; i += 8)
        t[i][threadIdx.x] = in[(size_t)(r0 + i) * C + c];
    __syncthreads();
    const int rr = r0 + threadIdx.x;
    const int cc = blockIdx.x * 32;
    for (int i = threadIdx.y; i < 32; i += 8)
        out[(size_t)(cc + i) * R + rr] = __float2half_rn(t[threadIdx.x][i]);
}

// Row softmax over 4096 cols: read fp32 scores, write fp16 P. One block per row.
__global__ __launch_bounds__(256) void softmax_h(
    const float* __restrict__ P, __half* __restrict__ Ph)
{
    const size_t row = blockIdx.x;
    const float2* p2 = reinterpret_cast<const float2*>(P + row * (size_t)SEQ);
    __half2* o2 = reinterpret_cast<__half2*>(Ph + row * (size_t)SEQ);
    const int tid = threadIdx.x;

    float2 v[8];
    float mx = -1e30f;
    #pragma unroll
    for (int i = 0; i < 8; i++) {
        v[i] = p2[i * 256 + tid];
        mx = fmaxf(mx, fmaxf(v[i].x, v[i].y));
    }

    __shared__ float red[8];
    #pragma unroll
    for (int off = 16; off; off >>= 1)
        mx = fmaxf(mx, __shfl_xor_sync(0xFFFFFFFFu, mx, off));
    if ((tid & 31) == 0) red[tid >> 5] = mx;
    __syncthreads();
    mx = red[0];
    #pragma unroll
    for (int w = 1; w < 8; w++) mx = fmaxf(mx, red[w]);

    float sum = 0.f;
    #pragma unroll
    for (int i = 0; i < 8; i++) {
        v[i].x = __expf(v[i].x - mx);
        v[i].y = __expf(v[i].y - mx);
        sum += v[i].x + v[i].y;
    }
    __syncthreads();
    #pragma unroll
    for (int off = 16; off; off >>= 1)
        sum += __shfl_xor_sync(0xFFFFFFFFu, sum, off);
    if ((tid & 31) == 0) red[tid >> 5] = sum;
    __syncthreads();
    sum = 0.f;
    #pragma unroll
    for (int w = 0; w < 8; w++) sum += red[w];

    const float inv = 1.f / sum;
    #pragma unroll
    for (int i = 0; i < 8; i++)
        o2[i * 256 + tid] = __floats2half2_rn(v[i].x * inv, v[i].y * inv);
}

extern "C" void kernel_launch(void* const* d_in, const int* in_sizes, int n_in,
                              void* d_out, int out_size)
{
    const float* x    = (const float*)d_in[0];
    const float* Wqkv = (const float*)d_in[1];
    const float* bqkv = (const float*)d_in[2];
    const float* Wo   = (const float*)d_in[3];
    const float* bo   = (const float*)d_in[4];
    float* out = (float*)d_out;

    __half *xh, *wqkvT, *woT, *qkvh, *vth, *attnh, *aouth;
    float *attn;
    cudaGetSymbolAddress((void**)&xh,    g_xh);
    cudaGetSymbolAddress((void**)&wqkvT, g_wqkvT);
    cudaGetSymbolAddress((void**)&woT,   g_woT);
    cudaGetSymbolAddress((void**)&qkvh,  g_qkvh);
    cudaGetSymbolAddress((void**)&vth,   g_vth);
    cudaGetSymbolAddress((void**)&attn,  g_attn);
    cudaGetSymbolAddress((void**)&attnh, g_attnh);
    cudaGetSymbolAddress((void**)&aouth, g_aouth);

    const int SMEM_DYN = NSTAGE * STAGE_BYTES;   // 98304 B
    cudaFuncSetAttribute(hgemm<0>, cudaFuncAttributeMaxDynamicSharedMemorySize, SMEM_DYN);
    cudaFuncSetAttribute(hgemm<1>, cudaFuncAttributeMaxDynamicSharedMemorySize, SMEM_DYN);
    cudaFuncSetAttribute(hgemm<2>, cudaFuncAttributeMaxDynamicSharedMemorySize, SMEM_DYN);

    const int BS = BATCH * SEQ;                      // 16384
    const long long sQKV = (long long)SEQ * 3 * DHEAD;
    const long long sATT = (long long)SEQ * SEQ;
    const long long sVT  = (long long)DHEAD * SEQ;
    const long long sOUT = (long long)SEQ * DHEAD;
    const float scale = 0.03125f;                    // 1/sqrt(1024)
    dim3 blk(256);

    // 0. fp16 conversions: x (elementwise), Wqkv^T and Wo^T (transpose)
    f2h_kernel<<<2048, 256>>>((const float4*)x, (uint2*)xh,
                              (size_t)BS * HID / 4);
    transpose_f2h<<<dim3(3 * DHEAD / 32, HID / 32), dim3(32, 8)>>>(Wqkv, wqkvT, HID, 3 * DHEAD);
    transpose_f2h<<<dim3(HID / 32, DHEAD / 32), dim3(32, 8)>>>(Wo, woT, DHEAD, HID);

    // 1. qkv = x @ Wqkv + bqkv  [16384 x 3072, K=4096]; q,k -> qkvh, v -> vth^T
    hgemm<2><<<dim3(3 * DHEAD / BN, BS / BM, 1), blk, SMEM_DYN>>>(
        xh, HID, 0, wqkvT, HID, 0, bqkv,
        nullptr, qkvh, vth, 3 * DHEAD, 0, HID, 1.f);

    // 2. scores = scale * Q @ K^T  (batched, K=1024) -> fp32 attn
    hgemm<0><<<dim3(SEQ / BN, SEQ / BM, BATCH), blk, SMEM_DYN>>>(
        qkvh, 3 * DHEAD, sQKV, qkvh + DHEAD, 3 * DHEAD, sQKV, nullptr,
        attn, nullptr, nullptr, SEQ, sATT, DHEAD, scale);

    // 3. softmax rows -> fp16 P
    softmax_h<<<BS, 256>>>(attn, attnh);

    // 4. out = P @ V  (batched, K=4096; B = V^T [1024][4096]) -> fp16 aout
    hgemm<1><<<dim3(DHEAD / BN, SEQ / BM, BATCH), blk, SMEM_DYN>>>(
        attnh, SEQ, sATT, vth, SEQ, sVT, nullptr,
        nullptr, aouth, nullptr, DHEAD, sOUT, SEQ, 1.f);

    // 5. y = out @ Wo + bo  [16384 x 4096, K=1024] -> fp32
    hgemm<0><<<dim3(HID / BN, BS / BM, 1), blk, SMEM_DYN>>>(
        aouth, DHEAD, 0, woT, DHEAD, 0, bo,
        out, nullptr, nullptr, HID, 0, DHEAD, 1.f);
}